// round 1
// baseline (speedup 1.0000x reference)
#include <cuda_runtime.h>
#include <cuda_bf16.h>
#include <cstdint>

#define NN 50000
#define EE 800000
#define REGSZ (NN * 128)

// ---------------- scratch (static device globals; no runtime alloc) ----------
__device__ int   g_deg[4 * NN];
__device__ int   g_cursor[4 * NN];
__device__ int   g_rowptr[4 * (NN + 1)];
__device__ float g_dinv[4 * NN];
__device__ int   g_csr_src[4 * EE];
__device__ float g_csr_coef[4 * EE];
__device__ float g_xw1[NN * 256];
__device__ float g_h[NN * 256];
__device__ float g_xw2[NN * 128];
__device__ int   g_is64[4];

// ---------------- edge dtype sniffing + decode -------------------------------
__global__ void detect_kernel(const void* e0, const void* e1, const void* e2, const void* e3) {
    if (threadIdx.x < 4) {
        const void* p = threadIdx.x == 0 ? e0 : threadIdx.x == 1 ? e1 : threadIdx.x == 2 ? e2 : e3;
        const unsigned int* u = (const unsigned int*)p;
        unsigned int acc = 0;
        // int64 little-endian: words at odd indices are high halves (== 0 since vals < 50000)
        for (int i = 0; i < 64; i++) acc |= u[2 * i + 1];
        g_is64[threadIdx.x] = (acc == 0) ? 1 : 0;
    }
}

__device__ __forceinline__ int2 load_edge(const void* ep, int is64, int e) {
    int s, d;
    if (is64) {
        const long long* p = (const long long*)ep;
        s = (int)p[e];
        d = (int)p[EE + e];
    } else {
        const int* p = (const int*)ep;
        s = p[e];
        d = p[EE + e];
    }
    return make_int2(s, d);
}

// ---------------- CSR build ---------------------------------------------------
__global__ void zero_int(int* p, int n) {
    int i = blockIdx.x * blockDim.x + threadIdx.x;
    if (i < n) p[i] = 0;
}

__global__ void build_deg(const void* ep, int r) {
    int e = blockIdx.x * blockDim.x + threadIdx.x;
    if (e >= EE) return;
    int2 sd = load_edge(ep, g_is64[r], e);
    atomicAdd(&g_deg[r * NN + sd.y], 1);
}

__global__ void calc_dinv() {
    int i = blockIdx.x * blockDim.x + threadIdx.x;
    if (i < 4 * NN) g_dinv[i] = rsqrtf((float)g_deg[i] + 1.0f);
}

__global__ void scan_rowptr() {
    int r = blockIdx.x;
    const int* deg = &g_deg[r * NN];
    int* rp = &g_rowptr[r * (NN + 1)];
    __shared__ int sh[1024];
    __shared__ int carry;
    if (threadIdx.x == 0) carry = 0;
    __syncthreads();
    for (int base = 0; base < NN; base += 1024) {
        int i = base + threadIdx.x;
        int v = (i < NN) ? deg[i] : 0;
        sh[threadIdx.x] = v;
        __syncthreads();
        for (int off = 1; off < 1024; off <<= 1) {
            int t = (threadIdx.x >= off) ? sh[threadIdx.x - off] : 0;
            __syncthreads();
            sh[threadIdx.x] += t;
            __syncthreads();
        }
        if (i < NN) rp[i] = carry + sh[threadIdx.x] - v;
        int total = sh[1023];
        __syncthreads();
        if (threadIdx.x == 0) carry += total;
        __syncthreads();
    }
    if (threadIdx.x == 0) rp[NN] = carry;
}

__global__ void build_csr(const void* ep, int r) {
    int e = blockIdx.x * blockDim.x + threadIdx.x;
    if (e >= EE) return;
    int2 sd = load_edge(ep, g_is64[r], e);
    int pos = g_rowptr[r * (NN + 1) + sd.y] + atomicAdd(&g_cursor[r * NN + sd.y], 1);
    g_csr_src[r * EE + pos] = sd.x;
    g_csr_coef[r * EE + pos] = g_dinv[r * NN + sd.x] * g_dinv[r * NN + sd.y];
}

// ---------------- GCN aggregation (gather by dst, fused self-loop+bias+lrelu) -
template <int F>
__global__ void agg_kernel(const float* __restrict__ xw, const float* __restrict__ bias,
                           float* __restrict__ out, int r) {
    int v = blockIdx.x;
    int t = threadIdx.x;  // 128 threads
    constexpr int J = F / 128;
    float acc[J];
#pragma unroll
    for (int j = 0; j < J; j++) acc[j] = 0.0f;

    const int* rp = &g_rowptr[r * (NN + 1)];
    const int* cs = &g_csr_src[r * EE];
    const float* cc = &g_csr_coef[r * EE];

    int beg = rp[v], end = rp[v + 1];
    for (int e = beg; e < end; e++) {
        int s = cs[e];
        float c = cc[e];
#pragma unroll
        for (int j = 0; j < J; j++)
            acc[j] += c * __ldg(&xw[s * F + t + j * 128]);
    }
    float dv = g_dinv[r * NN + v];
    float dv2 = dv * dv;
#pragma unroll
    for (int j = 0; j < J; j++) {
        float val = acc[j] + xw[v * F + t + j * 128] * dv2 + bias[t + j * 128];
        out[v * F + t + j * 128] = (val >= 0.0f) ? val : 0.2f * val;
    }
}

// ---------------- SGEMM: C[M,N] = A[M,256] @ W[256,N] (+opt bias + 0.5*(P+Q)) -
__global__ void sgemm_k256(const float* __restrict__ A, const float* __restrict__ W,
                           float* __restrict__ C, int M, int N,
                           const float* __restrict__ bias,
                           const float* __restrict__ P, const float* __restrict__ Q,
                           int comb) {
    const int K = 256;
    __shared__ float As[16][68];
    __shared__ float Ws[16][64];
    int tid = threadIdx.x;
    int tx = tid & 15, ty = tid >> 4;
    int m0 = blockIdx.y * 64, n0 = blockIdx.x * 64;

    float acc[4][4];
#pragma unroll
    for (int i = 0; i < 4; i++)
#pragma unroll
        for (int j = 0; j < 4; j++) acc[i][j] = 0.0f;

    int la_row = tid >> 2;         // 0..63
    int la_k = (tid & 3) * 4;      // 0,4,8,12
    int lw_k = tid >> 4;           // 0..15
    int lw_n = (tid & 15) * 4;     // 0..60

    for (int k0 = 0; k0 < K; k0 += 16) {
        float4 av = make_float4(0.f, 0.f, 0.f, 0.f);
        int arow = m0 + la_row;
        if (arow < M) av = *(const float4*)&A[arow * K + k0 + la_k];
        As[la_k + 0][la_row] = av.x;
        As[la_k + 1][la_row] = av.y;
        As[la_k + 2][la_row] = av.z;
        As[la_k + 3][la_row] = av.w;
        float4 wv = *(const float4*)&W[(k0 + lw_k) * N + n0 + lw_n];
        *(float4*)&Ws[lw_k][lw_n] = wv;
        __syncthreads();
#pragma unroll
        for (int k = 0; k < 16; k++) {
            float4 a4 = *(const float4*)&As[k][ty * 4];
            float4 b4 = *(const float4*)&Ws[k][tx * 4];
            float ar[4] = {a4.x, a4.y, a4.z, a4.w};
            float br[4] = {b4.x, b4.y, b4.z, b4.w};
#pragma unroll
            for (int i = 0; i < 4; i++)
#pragma unroll
                for (int j = 0; j < 4; j++) acc[i][j] += ar[i] * br[j];
        }
        __syncthreads();
    }

#pragma unroll
    for (int i = 0; i < 4; i++) {
        int row = m0 + ty * 4 + i;
        if (row >= M) continue;
#pragma unroll
        for (int j = 0; j < 4; j++) {
            int col = n0 + tx * 4 + j;
            float v = acc[i][j];
            if (comb)
                v += bias[col] + 0.5f * (P[row * N + col] + Q[row * N + col]);
            C[row * N + col] = v;
        }
    }
}

// ---------------- launch ------------------------------------------------------
extern "C" void kernel_launch(void* const* d_in, const int* in_sizes, int n_in,
                              void* d_out, int out_size) {
    const float* x[4] = {(const float*)d_in[0], (const float*)d_in[1],
                         (const float*)d_in[2], (const float*)d_in[3]};
    const void* ed[4] = {d_in[4], d_in[5], d_in[6], d_in[7]};
    const float* W1[4] = {(const float*)d_in[8], (const float*)d_in[10],
                          (const float*)d_in[16], (const float*)d_in[18]};
    const float* B1[4] = {(const float*)d_in[9], (const float*)d_in[11],
                          (const float*)d_in[17], (const float*)d_in[19]};
    const float* W2[4] = {(const float*)d_in[12], (const float*)d_in[14],
                          (const float*)d_in[20], (const float*)d_in[22]};
    const float* B2[4] = {(const float*)d_in[13], (const float*)d_in[15],
                          (const float*)d_in[21], (const float*)d_in[23]};
    float* out = (float*)d_out;

    float *xw1, *h, *xw2;
    int *degp, *curp;
    cudaGetSymbolAddress((void**)&xw1, g_xw1);
    cudaGetSymbolAddress((void**)&h, g_h);
    cudaGetSymbolAddress((void**)&xw2, g_xw2);
    cudaGetSymbolAddress((void**)&degp, g_deg);
    cudaGetSymbolAddress((void**)&curp, g_cursor);

    detect_kernel<<<1, 32>>>(ed[0], ed[1], ed[2], ed[3]);
    zero_int<<<(4 * NN + 255) / 256, 256>>>(degp, 4 * NN);
    zero_int<<<(4 * NN + 255) / 256, 256>>>(curp, 4 * NN);
    for (int r = 0; r < 4; r++) build_deg<<<(EE + 255) / 256, 256>>>(ed[r], r);
    calc_dinv<<<(4 * NN + 255) / 256, 256>>>();
    scan_rowptr<<<4, 1024>>>();
    for (int r = 0; r < 4; r++) build_csr<<<(EE + 255) / 256, 256>>>(ed[r], r);

    dim3 g256(4, (NN + 63) / 64);
    dim3 g128(2, (NN + 63) / 64);
    for (int p = 0; p < 4; p++) {
        // layer 1: xw1 = x @ W1 ; h = lrelu(agg + self + b1)
        sgemm_k256<<<g256, 256>>>(x[p], W1[p], xw1, NN, 256, nullptr, nullptr, nullptr, 0);
        agg_kernel<256><<<NN, 128>>>(xw1, B1[p], h, p);
        // layer 2: xw2 = h @ W2 ; out_region = lrelu(agg + self + b2)
        sgemm_k256<<<g128, 256>>>(h, W2[p], xw2, NN, 128, nullptr, nullptr, nullptr, 0);
        agg_kernel<128><<<NN, 128>>>(xw2, B2[p], out + (size_t)(2 + p) * REGSZ, p);
    }
    // comb_l = 0.5*(jl+bl) + x_lnc_jac @ W_res_lnc + b_res_lnc
    sgemm_k256<<<g128, 256>>>(x[0], (const float*)d_in[24], out, NN, 128,
                              (const float*)d_in[25], out + (size_t)2 * REGSZ,
                              out + (size_t)4 * REGSZ, 1);
    // comb_p = 0.5*(jp+bp) + x_prot_jac @ W_res_prot + b_res_prot
    sgemm_k256<<<g128, 256>>>(x[1], (const float*)d_in[26], out + (size_t)REGSZ, NN, 128,
                              (const float*)d_in[27], out + (size_t)3 * REGSZ,
                              out + (size_t)5 * REGSZ, 1);
}

// round 2
// speedup vs baseline: 1.0854x; 1.0854x over previous
#include <cuda_runtime.h>
#include <cuda_bf16.h>
#include <cstdint>

#define NN 50000
#define EE 800000
#define REGSZ (NN * 128)
#define CHUNK 512
#define NCHUNK ((NN + CHUNK - 1) / CHUNK)   // 98

// ---------------- scratch (static device globals; no runtime alloc) ----------
__device__ int   g_deg[4 * NN];
__device__ int   g_cursor[4 * NN];
__device__ int   g_rowptr[4 * (NN + 1)];
__device__ float g_dinv[4 * NN];
__device__ int   g_csr_src[4 * EE];
__device__ float g_csr_coef[4 * EE];
__device__ float g_xw1[NN * 256];
__device__ float g_h[NN * 256];
__device__ float g_xw2[NN * 128];
__device__ int   g_is64[4];
__device__ int   g_chunksum[4 * NCHUNK];
__device__ int   g_chunkoff[4 * NCHUNK];

// ---------------- f32x2 packed helpers ---------------------------------------
__device__ __forceinline__ void ffma2(unsigned long long& acc, unsigned long long a,
                                      unsigned long long b) {
    asm("fma.rn.f32x2 %0, %1, %2, %0;" : "+l"(acc) : "l"(a), "l"(b));
}
__device__ __forceinline__ unsigned long long dup2(float x) {
    unsigned long long r;
    unsigned int u = __float_as_uint(x);
    asm("mov.b64 %0, {%1, %1};" : "=l"(r) : "r"(u));
    return r;
}
__device__ __forceinline__ float2 unpk(unsigned long long v) {
    unsigned int lo, hi;
    asm("mov.b64 {%0, %1}, %2;" : "=r"(lo), "=r"(hi) : "l"(v));
    return make_float2(__uint_as_float(lo), __uint_as_float(hi));
}

// ---------------- edge dtype sniffing + decode -------------------------------
__global__ void detect_kernel(const void* e0, const void* e1, const void* e2, const void* e3) {
    if (threadIdx.x < 4) {
        const void* p = threadIdx.x == 0 ? e0 : threadIdx.x == 1 ? e1 : threadIdx.x == 2 ? e2 : e3;
        const unsigned int* u = (const unsigned int*)p;
        unsigned int acc = 0;
        for (int i = 0; i < 64; i++) acc |= u[2 * i + 1];
        g_is64[threadIdx.x] = (acc == 0) ? 1 : 0;
    }
}

__device__ __forceinline__ int2 load_edge(const void* ep, int is64, int e) {
    int s, d;
    if (is64) {
        const long long* p = (const long long*)ep;
        s = (int)p[e];
        d = (int)p[EE + e];
    } else {
        const int* p = (const int*)ep;
        s = p[e];
        d = p[EE + e];
    }
    return make_int2(s, d);
}

// ---------------- CSR build ---------------------------------------------------
__global__ void zero_counts() {
    int i = blockIdx.x * blockDim.x + threadIdx.x;
    if (i < 4 * NN) { g_deg[i] = 0; g_cursor[i] = 0; }
}

__global__ void build_deg(const void* e0, const void* e1, const void* e2, const void* e3) {
    int e = blockIdx.x * blockDim.x + threadIdx.x;
    int r = blockIdx.y;
    if (e >= EE) return;
    const void* ep = r == 0 ? e0 : r == 1 ? e1 : r == 2 ? e2 : e3;
    int2 sd = load_edge(ep, g_is64[r], e);
    atomicAdd(&g_deg[r * NN + sd.y], 1);
}

__global__ void calc_dinv() {
    int i = blockIdx.x * blockDim.x + threadIdx.x;
    if (i < 4 * NN) g_dinv[i] = rsqrtf((float)g_deg[i] + 1.0f);
}

// 3-phase parallel exclusive scan of g_deg -> g_rowptr (per relation)
__global__ void scan_p1() {  // grid (NCHUNK, 4), block 512
    int r = blockIdx.y;
    int i = blockIdx.x * CHUNK + threadIdx.x;
    int v = (i < NN) ? g_deg[r * NN + i] : 0;
    __shared__ int sh[CHUNK];
    sh[threadIdx.x] = v;
    __syncthreads();
    for (int off = CHUNK / 2; off > 0; off >>= 1) {
        if (threadIdx.x < off) sh[threadIdx.x] += sh[threadIdx.x + off];
        __syncthreads();
    }
    if (threadIdx.x == 0) g_chunksum[r * NCHUNK + blockIdx.x] = sh[0];
}

__global__ void scan_p2() {  // grid 4, block 128
    int r = blockIdx.x;
    __shared__ int sh[128];
    int v = (threadIdx.x < NCHUNK) ? g_chunksum[r * NCHUNK + threadIdx.x] : 0;
    sh[threadIdx.x] = v;
    __syncthreads();
    for (int off = 1; off < 128; off <<= 1) {
        int t = (threadIdx.x >= off) ? sh[threadIdx.x - off] : 0;
        __syncthreads();
        sh[threadIdx.x] += t;
        __syncthreads();
    }
    if (threadIdx.x < NCHUNK) g_chunkoff[r * NCHUNK + threadIdx.x] = sh[threadIdx.x] - v;
    if (threadIdx.x == 127) g_rowptr[r * (NN + 1) + NN] = sh[127];
}

__global__ void scan_p3() {  // grid (NCHUNK, 4), block 512
    int r = blockIdx.y;
    int i = blockIdx.x * CHUNK + threadIdx.x;
    int v = (i < NN) ? g_deg[r * NN + i] : 0;
    __shared__ int sh[CHUNK];
    sh[threadIdx.x] = v;
    __syncthreads();
    for (int off = 1; off < CHUNK; off <<= 1) {
        int t = (threadIdx.x >= off) ? sh[threadIdx.x - off] : 0;
        __syncthreads();
        sh[threadIdx.x] += t;
        __syncthreads();
    }
    if (i < NN)
        g_rowptr[r * (NN + 1) + i] = g_chunkoff[r * NCHUNK + blockIdx.x] + sh[threadIdx.x] - v;
}

__global__ void build_csr(const void* e0, const void* e1, const void* e2, const void* e3) {
    int e = blockIdx.x * blockDim.x + threadIdx.x;
    int r = blockIdx.y;
    if (e >= EE) return;
    const void* ep = r == 0 ? e0 : r == 1 ? e1 : r == 2 ? e2 : e3;
    int2 sd = load_edge(ep, g_is64[r], e);
    int pos = g_rowptr[r * (NN + 1) + sd.y] + atomicAdd(&g_cursor[r * NN + sd.y], 1);
    g_csr_src[r * EE + pos] = sd.x;
    g_csr_coef[r * EE + pos] = g_dinv[r * NN + sd.x] * g_dinv[r * NN + sd.y];
}

// ---------------- GCN aggregation (gather by dst, fused self-loop+bias+lrelu) -
template <int F>
__global__ void agg_kernel(const float* __restrict__ xw, const float* __restrict__ bias,
                           float* __restrict__ out, int r) {
    int v = blockIdx.x;
    int t = threadIdx.x;  // 128 threads
    constexpr int J = F / 128;
    float acc[J];
#pragma unroll
    for (int j = 0; j < J; j++) acc[j] = 0.0f;

    const int* rp = &g_rowptr[r * (NN + 1)];
    const int* cs = &g_csr_src[r * EE];
    const float* cc = &g_csr_coef[r * EE];

    int beg = rp[v], end = rp[v + 1];
    for (int e = beg; e < end; e++) {
        int s = cs[e];
        float c = cc[e];
#pragma unroll
        for (int j = 0; j < J; j++)
            acc[j] += c * __ldg(&xw[s * F + t + j * 128]);
    }
    float dv = g_dinv[r * NN + v];
    float dv2 = dv * dv;
#pragma unroll
    for (int j = 0; j < J; j++) {
        float val = acc[j] + xw[v * F + t + j * 128] * dv2 + bias[t + j * 128];
        out[v * F + t + j * 128] = (val >= 0.0f) ? val : 0.2f * val;
    }
}

// ---------------- SGEMM via FFMA2: C[M,N] = A[M,256] @ W[256,N] ---------------
// optional epilogue: + bias + 0.5*(P+Q)
__global__ void sgemm_k256(const float* __restrict__ A, const float* __restrict__ W,
                           float* __restrict__ C, int M, int N,
                           const float* __restrict__ bias,
                           const float* __restrict__ P, const float* __restrict__ Q,
                           int comb) {
    const int K = 256;
    __shared__ __align__(16) float As[2][16][68];
    __shared__ __align__(16) float Ws[2][16][64];
    int tid = threadIdx.x;
    int tx = tid & 15, ty = tid >> 4;
    int m0 = blockIdx.y * 64, n0 = blockIdx.x * 64;

    // acc[i2][j]: packed rows {ty*4+2*i2, ty*4+2*i2+1}, col tx*4+j
    unsigned long long acc[2][4];
#pragma unroll
    for (int i = 0; i < 2; i++)
#pragma unroll
        for (int j = 0; j < 4; j++) acc[i][j] = 0ull;

    int la_row = tid >> 2;      // 0..63
    int la_k = (tid & 3) * 4;   // 0,4,8,12
    int lw_k = tid >> 4;        // 0..15
    int lw_n = (tid & 15) * 4;  // 0..60
    int arow = m0 + la_row;
    bool aok = arow < M;

    float4 av = make_float4(0.f, 0.f, 0.f, 0.f);
    if (aok) av = *(const float4*)&A[arow * K + la_k];
    float4 wv = *(const float4*)&W[lw_k * N + n0 + lw_n];

    int buf = 0;
    for (int k0 = 0; k0 < K; k0 += 16) {
        As[buf][la_k + 0][la_row] = av.x;
        As[buf][la_k + 1][la_row] = av.y;
        As[buf][la_k + 2][la_row] = av.z;
        As[buf][la_k + 3][la_row] = av.w;
        *(float4*)&Ws[buf][lw_k][lw_n] = wv;
        __syncthreads();
        if (k0 + 16 < K) {
            if (aok) av = *(const float4*)&A[arow * K + (k0 + 16) + la_k];
            wv = *(const float4*)&W[(k0 + 16 + lw_k) * N + n0 + lw_n];
        }
#pragma unroll
        for (int k = 0; k < 16; k++) {
            ulonglong2 aU = *(const ulonglong2*)&As[buf][k][ty * 4];
            float4 b4 = *(const float4*)&Ws[buf][k][tx * 4];
            unsigned long long b0 = dup2(b4.x), b1 = dup2(b4.y), b2 = dup2(b4.z), b3 = dup2(b4.w);
            ffma2(acc[0][0], aU.x, b0);
            ffma2(acc[1][0], aU.y, b0);
            ffma2(acc[0][1], aU.x, b1);
            ffma2(acc[1][1], aU.y, b1);
            ffma2(acc[0][2], aU.x, b2);
            ffma2(acc[1][2], aU.y, b2);
            ffma2(acc[0][3], aU.x, b3);
            ffma2(acc[1][3], aU.y, b3);
        }
        buf ^= 1;
    }

#pragma unroll
    for (int i2 = 0; i2 < 2; i2++) {
        float2 c0 = unpk(acc[i2][0]), c1 = unpk(acc[i2][1]);
        float2 c2 = unpk(acc[i2][2]), c3 = unpk(acc[i2][3]);
#pragma unroll
        for (int rr = 0; rr < 2; rr++) {
            int row = m0 + ty * 4 + i2 * 2 + rr;
            if (row >= M) continue;
            int col = n0 + tx * 4;
            float4 o;
            o.x = rr ? c0.y : c0.x;
            o.y = rr ? c1.y : c1.x;
            o.z = rr ? c2.y : c2.x;
            o.w = rr ? c3.y : c3.x;
            if (comb) {
                float4 p4 = *(const float4*)&P[row * N + col];
                float4 q4 = *(const float4*)&Q[row * N + col];
                o.x += bias[col + 0] + 0.5f * (p4.x + q4.x);
                o.y += bias[col + 1] + 0.5f * (p4.y + q4.y);
                o.z += bias[col + 2] + 0.5f * (p4.z + q4.z);
                o.w += bias[col + 3] + 0.5f * (p4.w + q4.w);
            }
            *(float4*)&C[row * N + col] = o;
        }
    }
}

// ---------------- launch ------------------------------------------------------
extern "C" void kernel_launch(void* const* d_in, const int* in_sizes, int n_in,
                              void* d_out, int out_size) {
    const float* x[4] = {(const float*)d_in[0], (const float*)d_in[1],
                         (const float*)d_in[2], (const float*)d_in[3]};
    const void* ed[4] = {d_in[4], d_in[5], d_in[6], d_in[7]};
    const float* W1[4] = {(const float*)d_in[8], (const float*)d_in[10],
                          (const float*)d_in[16], (const float*)d_in[18]};
    const float* B1[4] = {(const float*)d_in[9], (const float*)d_in[11],
                          (const float*)d_in[17], (const float*)d_in[19]};
    const float* W2[4] = {(const float*)d_in[12], (const float*)d_in[14],
                          (const float*)d_in[20], (const float*)d_in[22]};
    const float* B2[4] = {(const float*)d_in[13], (const float*)d_in[15],
                          (const float*)d_in[21], (const float*)d_in[23]};
    float* out = (float*)d_out;

    float *xw1, *h, *xw2;
    cudaGetSymbolAddress((void**)&xw1, g_xw1);
    cudaGetSymbolAddress((void**)&h, g_h);
    cudaGetSymbolAddress((void**)&xw2, g_xw2);

    detect_kernel<<<1, 32>>>(ed[0], ed[1], ed[2], ed[3]);
    zero_counts<<<(4 * NN + 255) / 256, 256>>>();
    build_deg<<<dim3((EE + 255) / 256, 4), 256>>>(ed[0], ed[1], ed[2], ed[3]);
    calc_dinv<<<(4 * NN + 255) / 256, 256>>>();
    scan_p1<<<dim3(NCHUNK, 4), CHUNK>>>();
    scan_p2<<<4, 128>>>();
    scan_p3<<<dim3(NCHUNK, 4), CHUNK>>>();
    build_csr<<<dim3((EE + 255) / 256, 4), 256>>>(ed[0], ed[1], ed[2], ed[3]);

    dim3 g256(4, (NN + 63) / 64);
    dim3 g128(2, (NN + 63) / 64);
    for (int p = 0; p < 4; p++) {
        sgemm_k256<<<g256, 256>>>(x[p], W1[p], xw1, NN, 256, nullptr, nullptr, nullptr, 0);
        agg_kernel<256><<<NN, 128>>>(xw1, B1[p], h, p);
        sgemm_k256<<<g128, 256>>>(h, W2[p], xw2, NN, 128, nullptr, nullptr, nullptr, 0);
        agg_kernel<128><<<NN, 128>>>(xw2, B2[p], out + (size_t)(2 + p) * REGSZ, p);
    }
    sgemm_k256<<<g128, 256>>>(x[0], (const float*)d_in[24], out, NN, 128,
                              (const float*)d_in[25], out + (size_t)2 * REGSZ,
                              out + (size_t)4 * REGSZ, 1);
    sgemm_k256<<<g128, 256>>>(x[1], (const float*)d_in[26], out + (size_t)REGSZ, NN, 128,
                              (const float*)d_in[27], out + (size_t)3 * REGSZ,
                              out + (size_t)5 * REGSZ, 1);
}

// round 4
// speedup vs baseline: 1.4219x; 1.3100x over previous
#include <cuda_runtime.h>
#include <cuda_bf16.h>
#include <cstdint>

#define NN 50000
#define EE 800000
#define REGSZ (NN * 128)
#define CHUNK 512
#define NCHUNK ((NN + CHUNK - 1) / CHUNK)   // 98

// ---------------- scratch (static device globals; no runtime alloc) ----------
__device__ int   g_deg[4 * NN];
__device__ int   g_cursor[4 * NN];
__device__ int   g_rowptr[4 * (NN + 1)];
__device__ float g_dinv[4 * NN];
__device__ int   g_csr_src[4 * EE];
__device__ float g_csr_coef[4 * EE];
__device__ float g_xw1[NN * 256];
__device__ float g_h[NN * 256];
__device__ float g_xw2[NN * 128];
__device__ int   g_is64[4];
__device__ int   g_chunksum[4 * NCHUNK];
__device__ int   g_chunkoff[4 * NCHUNK];
// bf16-split activation + weight buffers (weights stored transposed [n][k])
__device__ __nv_bfloat16 g_Ahi[NN * 256];
__device__ __nv_bfloat16 g_Alo[NN * 256];
#define WOFF1(p) ((p) * 65536)
#define WOFF2(p) (262144 + (p) * 32768)
#define WOFFR(i) (393216 + (i) * 32768)
__device__ __nv_bfloat16 g_Whi[458752];
__device__ __nv_bfloat16 g_Wlo[458752];

// ---------------- mma.sync helpers -------------------------------------------
__device__ __forceinline__ uint32_t smem_u32(const void* p) {
    uint32_t a;
    asm("{ .reg .u64 t; cvta.to.shared.u64 t, %1; cvt.u32.u64 %0, t; }" : "=r"(a) : "l"(p));
    return a;
}
__device__ __forceinline__ void ldsm4(uint32_t& r0, uint32_t& r1, uint32_t& r2, uint32_t& r3,
                                      uint32_t a) {
    asm volatile("ldmatrix.sync.aligned.m8n8.x4.shared.b16 {%0,%1,%2,%3}, [%4];"
                 : "=r"(r0), "=r"(r1), "=r"(r2), "=r"(r3) : "r"(a));
}
__device__ __forceinline__ void mma16816(float* d, const uint32_t* a, const uint32_t* b) {
    asm volatile(
        "mma.sync.aligned.m16n8k16.row.col.f32.bf16.bf16.f32 "
        "{%0,%1,%2,%3}, {%4,%5,%6,%7}, {%8,%9}, {%0,%1,%2,%3};"
        : "+f"(d[0]), "+f"(d[1]), "+f"(d[2]), "+f"(d[3])
        : "r"(a[0]), "r"(a[1]), "r"(a[2]), "r"(a[3]), "r"(b[0]), "r"(b[1]));
}

// ---------------- edge dtype sniffing + decode -------------------------------
__global__ void detect_kernel(const void* e0, const void* e1, const void* e2, const void* e3) {
    if (threadIdx.x < 4) {
        const void* p = threadIdx.x == 0 ? e0 : threadIdx.x == 1 ? e1 : threadIdx.x == 2 ? e2 : e3;
        const unsigned int* u = (const unsigned int*)p;
        unsigned int acc = 0;
        for (int i = 0; i < 64; i++) acc |= u[2 * i + 1];
        g_is64[threadIdx.x] = (acc == 0) ? 1 : 0;
    }
}

__device__ __forceinline__ int2 load_edge(const void* ep, int is64, int e) {
    int s, d;
    if (is64) {
        const long long* p = (const long long*)ep;
        s = (int)p[e];
        d = (int)p[EE + e];
    } else {
        const int* p = (const int*)ep;
        s = p[e];
        d = p[EE + e];
    }
    return make_int2(s, d);
}

// ---------------- CSR build ---------------------------------------------------
__global__ void zero_counts() {
    int i = blockIdx.x * blockDim.x + threadIdx.x;
    if (i < 4 * NN) { g_deg[i] = 0; g_cursor[i] = 0; }
}

__global__ void build_deg(const void* e0, const void* e1, const void* e2, const void* e3) {
    int e = blockIdx.x * blockDim.x + threadIdx.x;
    int r = blockIdx.y;
    if (e >= EE) return;
    const void* ep = r == 0 ? e0 : r == 1 ? e1 : r == 2 ? e2 : e3;
    int2 sd = load_edge(ep, g_is64[r], e);
    atomicAdd(&g_deg[r * NN + sd.y], 1);
}

__global__ void calc_dinv() {
    int i = blockIdx.x * blockDim.x + threadIdx.x;
    if (i < 4 * NN) g_dinv[i] = rsqrtf((float)g_deg[i] + 1.0f);
}

__global__ void scan_p1() {
    int r = blockIdx.y;
    int i = blockIdx.x * CHUNK + threadIdx.x;
    int v = (i < NN) ? g_deg[r * NN + i] : 0;
    __shared__ int sh[CHUNK];
    sh[threadIdx.x] = v;
    __syncthreads();
    for (int off = CHUNK / 2; off > 0; off >>= 1) {
        if (threadIdx.x < off) sh[threadIdx.x] += sh[threadIdx.x + off];
        __syncthreads();
    }
    if (threadIdx.x == 0) g_chunksum[r * NCHUNK + blockIdx.x] = sh[0];
}

__global__ void scan_p2() {
    int r = blockIdx.x;
    __shared__ int sh[128];
    int v = (threadIdx.x < NCHUNK) ? g_chunksum[r * NCHUNK + threadIdx.x] : 0;
    sh[threadIdx.x] = v;
    __syncthreads();
    for (int off = 1; off < 128; off <<= 1) {
        int t = (threadIdx.x >= off) ? sh[threadIdx.x - off] : 0;
        __syncthreads();
        sh[threadIdx.x] += t;
        __syncthreads();
    }
    if (threadIdx.x < NCHUNK) g_chunkoff[r * NCHUNK + threadIdx.x] = sh[threadIdx.x] - v;
    if (threadIdx.x == 127) g_rowptr[r * (NN + 1) + NN] = sh[127];
}

__global__ void scan_p3() {
    int r = blockIdx.y;
    int i = blockIdx.x * CHUNK + threadIdx.x;
    int v = (i < NN) ? g_deg[r * NN + i] : 0;
    __shared__ int sh[CHUNK];
    sh[threadIdx.x] = v;
    __syncthreads();
    for (int off = 1; off < CHUNK; off <<= 1) {
        int t = (threadIdx.x >= off) ? sh[threadIdx.x - off] : 0;
        __syncthreads();
        sh[threadIdx.x] += t;
        __syncthreads();
    }
    if (i < NN)
        g_rowptr[r * (NN + 1) + i] = g_chunkoff[r * NCHUNK + blockIdx.x] + sh[threadIdx.x] - v;
}

__global__ void build_csr(const void* e0, const void* e1, const void* e2, const void* e3) {
    int e = blockIdx.x * blockDim.x + threadIdx.x;
    int r = blockIdx.y;
    if (e >= EE) return;
    const void* ep = r == 0 ? e0 : r == 1 ? e1 : r == 2 ? e2 : e3;
    int2 sd = load_edge(ep, g_is64[r], e);
    int pos = g_rowptr[r * (NN + 1) + sd.y] + atomicAdd(&g_cursor[r * NN + sd.y], 1);
    g_csr_src[r * EE + pos] = sd.x;
    g_csr_coef[r * EE + pos] = g_dinv[r * NN + sd.x] * g_dinv[r * NN + sd.y];
}

// ---------------- bf16 split conversions --------------------------------------
__global__ void convA(const float* __restrict__ x, __nv_bfloat16* __restrict__ hi,
                      __nv_bfloat16* __restrict__ lo, int n4) {
    int i = blockIdx.x * 256 + threadIdx.x;
    if (i >= n4) return;
    float4 v = ((const float4*)x)[i];
    __nv_bfloat16 h0 = __float2bfloat16(v.x);
    __nv_bfloat16 h1 = __float2bfloat16(v.y);
    __nv_bfloat16 h2 = __float2bfloat16(v.z);
    __nv_bfloat16 h3 = __float2bfloat16(v.w);
    __nv_bfloat162* hp = (__nv_bfloat162*)&hi[i * 4];
    hp[0] = __nv_bfloat162(h0, h1);
    hp[1] = __nv_bfloat162(h2, h3);
    __nv_bfloat162* lp = (__nv_bfloat162*)&lo[i * 4];
    lp[0] = __nv_bfloat162(__float2bfloat16(v.x - __bfloat162float(h0)),
                           __float2bfloat16(v.y - __bfloat162float(h1)));
    lp[1] = __nv_bfloat162(__float2bfloat16(v.z - __bfloat162float(h2)),
                           __float2bfloat16(v.w - __bfloat162float(h3)));
}

// W[k,N] fp32 -> Wt[n,k] bf16 hi/lo (K fixed = 256)
__global__ void convW(const float* __restrict__ W, __nv_bfloat16* __restrict__ hi,
                      __nv_bfloat16* __restrict__ lo, int N) {
    int i = blockIdx.x * 256 + threadIdx.x;
    if (i >= N * 256) return;
    int n = i >> 8, k = i & 255;
    float v = W[k * N + n];
    __nv_bfloat16 h = __float2bfloat16(v);
    hi[i] = h;
    lo[i] = __float2bfloat16(v - __bfloat162float(h));
}

// ---------------- mma.sync GEMM: C[M,Ntot] = A @ Wt^T (3-term bf16 split) -----
// block tile 128(M) x 64(N), K streamed in chunks of 64 via smem (LDA=72 pad)
#define LDA 72
#define OFF_AHI 0
#define OFF_ALO (128 * LDA)
#define OFF_BHI (2 * 128 * LDA)
#define OFF_BLO (2 * 128 * LDA + 64 * LDA)
#define SM_ELEMS (2 * 128 * LDA + 2 * 64 * LDA)   // 27648 bf16 = 55296 B

__global__ void __launch_bounds__(256, 2) gemm_mma(
    const __nv_bfloat16* __restrict__ Ahi, const __nv_bfloat16* __restrict__ Alo,
    const __nv_bfloat16* __restrict__ Bhi, const __nv_bfloat16* __restrict__ Blo,
    float* __restrict__ C, int M, int Ntot,
    const float* __restrict__ bias, const float* __restrict__ P,
    const float* __restrict__ Q, int comb) {
    extern __shared__ __nv_bfloat16 sm[];
    uint32_t sb = smem_u32(sm);
    int tid = threadIdx.x, lane = tid & 31, w = tid >> 5;
    int wm = w & 3, wn = w >> 2;            // 4 warps M x 2 warps N
    int m0 = blockIdx.y * 128, n0 = blockIdx.x * 64;

    float acc[2][4][4];
#pragma unroll
    for (int mi = 0; mi < 2; mi++)
#pragma unroll
        for (int ni = 0; ni < 4; ni++)
#pragma unroll
            for (int q = 0; q < 4; q++) acc[mi][ni][q] = 0.0f;

    // ldmatrix source offsets (elements)
    uint32_t a_off[2], b_off[2];
#pragma unroll
    for (int mi = 0; mi < 2; mi++)
        a_off[mi] = (uint32_t)((wm * 32 + mi * 16 + (lane & 15)) * LDA + (lane >> 4) * 8);
#pragma unroll
    for (int bt = 0; bt < 2; bt++)
        b_off[bt] = (uint32_t)((wn * 32 + bt * 16 + ((lane >> 4) << 3) + (lane & 7)) * LDA +
                               ((lane >> 3) & 1) * 8);

    for (int k0 = 0; k0 < 256; k0 += 64) {
        // stage A chunk [128 x 64] hi/lo
#pragma unroll
        for (int i = 0; i < 4; i++) {
            int idx = tid + i * 256;
            int row = idx >> 3, col = (idx & 7) * 8;
            uint4 vh = make_uint4(0, 0, 0, 0), vl = make_uint4(0, 0, 0, 0);
            if (m0 + row < M) {
                vh = *(const uint4*)&Ahi[(size_t)(m0 + row) * 256 + k0 + col];
                vl = *(const uint4*)&Alo[(size_t)(m0 + row) * 256 + k0 + col];
            }
            *(uint4*)&sm[OFF_AHI + row * LDA + col] = vh;
            *(uint4*)&sm[OFF_ALO + row * LDA + col] = vl;
        }
        // stage B chunk [64 x 64] hi/lo
#pragma unroll
        for (int i = 0; i < 2; i++) {
            int idx = tid + i * 256;
            int row = idx >> 3, col = (idx & 7) * 8;
            *(uint4*)&sm[OFF_BHI + row * LDA + col] =
                *(const uint4*)&Bhi[(size_t)(n0 + row) * 256 + k0 + col];
            *(uint4*)&sm[OFF_BLO + row * LDA + col] =
                *(const uint4*)&Blo[(size_t)(n0 + row) * 256 + k0 + col];
        }
        __syncthreads();

#pragma unroll
        for (int ks = 0; ks < 4; ks++) {
            int k = ks * 16;
            uint32_t aH[2][4], aL[2][4], bH[4][2], bL[4][2];
#pragma unroll
            for (int mi = 0; mi < 2; mi++) {
                uint32_t ah = sb + ((OFF_AHI + a_off[mi] + k) << 1);
                uint32_t al = sb + ((OFF_ALO + a_off[mi] + k) << 1);
                ldsm4(aH[mi][0], aH[mi][1], aH[mi][2], aH[mi][3], ah);
                ldsm4(aL[mi][0], aL[mi][1], aL[mi][2], aL[mi][3], al);
            }
#pragma unroll
            for (int bt = 0; bt < 2; bt++) {
                uint32_t bh = sb + ((OFF_BHI + b_off[bt] + k) << 1);
                uint32_t bl = sb + ((OFF_BLO + b_off[bt] + k) << 1);
                uint32_t r0, r1, r2, r3;
                ldsm4(r0, r1, r2, r3, bh);
                bH[bt * 2][0] = r0; bH[bt * 2][1] = r1;
                bH[bt * 2 + 1][0] = r2; bH[bt * 2 + 1][1] = r3;
                ldsm4(r0, r1, r2, r3, bl);
                bL[bt * 2][0] = r0; bL[bt * 2][1] = r1;
                bL[bt * 2 + 1][0] = r2; bL[bt * 2 + 1][1] = r3;
            }
#pragma unroll
            for (int mi = 0; mi < 2; mi++)
#pragma unroll
                for (int ni = 0; ni < 4; ni++) {
                    mma16816(acc[mi][ni], aH[mi], bH[ni]);
                    mma16816(acc[mi][ni], aH[mi], bL[ni]);
                    mma16816(acc[mi][ni], aL[mi], bH[ni]);
                }
        }
        __syncthreads();
    }

    // epilogue
#pragma unroll
    for (int mi = 0; mi < 2; mi++) {
#pragma unroll
        for (int ni = 0; ni < 4; ni++) {
            int col = n0 + wn * 32 + ni * 8 + (lane & 3) * 2;
            int r_lo = m0 + wm * 32 + mi * 16 + (lane >> 2);
            int r_hi = r_lo + 8;
#pragma unroll
            for (int half = 0; half < 2; half++) {
                int row = half ? r_hi : r_lo;
                if (row >= M) continue;
                float2 o;
                o.x = acc[mi][ni][half * 2 + 0];
                o.y = acc[mi][ni][half * 2 + 1];
                size_t base = (size_t)row * Ntot + col;
                if (comb) {
                    o.x += bias[col] + 0.5f * (P[base] + Q[base]);
                    o.y += bias[col + 1] + 0.5f * (P[base + 1] + Q[base + 1]);
                }
                *(float2*)&C[base] = o;
            }
        }
    }
}

// ---------------- GCN aggregation (gather by dst, fused self-loop+bias+lrelu) -
template <int F>
__global__ void agg_kernel(const float* __restrict__ xw, const float* __restrict__ bias,
                           float* __restrict__ out, int r) {
    int v = blockIdx.x;
    int t = threadIdx.x;  // 128 threads
    constexpr int J = F / 128;
    float acc[J];
#pragma unroll
    for (int j = 0; j < J; j++) acc[j] = 0.0f;

    const int* rp = &g_rowptr[r * (NN + 1)];
    const int* cs = &g_csr_src[r * EE];
    const float* cc = &g_csr_coef[r * EE];

    int beg = rp[v], end = rp[v + 1];
    for (int e = beg; e < end; e++) {
        int s = cs[e];
        float c = cc[e];
#pragma unroll
        for (int j = 0; j < J; j++)
            acc[j] += c * __ldg(&xw[s * F + t + j * 128]);
    }
    float dv = g_dinv[r * NN + v];
    float dv2 = dv * dv;
#pragma unroll
    for (int j = 0; j < J; j++) {
        float val = acc[j] + xw[v * F + t + j * 128] * dv2 + bias[t + j * 128];
        out[v * F + t + j * 128] = (val >= 0.0f) ? val : 0.2f * val;
    }
}

// ---------------- launch ------------------------------------------------------
extern "C" void kernel_launch(void* const* d_in, const int* in_sizes, int n_in,
                              void* d_out, int out_size) {
    const float* x[4] = {(const float*)d_in[0], (const float*)d_in[1],
                         (const float*)d_in[2], (const float*)d_in[3]};
    const void* ed[4] = {d_in[4], d_in[5], d_in[6], d_in[7]};
    const float* W1[4] = {(const float*)d_in[8], (const float*)d_in[10],
                          (const float*)d_in[16], (const float*)d_in[18]};
    const float* B1[4] = {(const float*)d_in[9], (const float*)d_in[11],
                          (const float*)d_in[17], (const float*)d_in[19]};
    const float* W2[4] = {(const float*)d_in[12], (const float*)d_in[14],
                          (const float*)d_in[20], (const float*)d_in[22]};
    const float* B2[4] = {(const float*)d_in[13], (const float*)d_in[15],
                          (const float*)d_in[21], (const float*)d_in[23]};
    float* out = (float*)d_out;

    float *xw1, *h, *xw2;
    __nv_bfloat16 *ahi, *alo, *whi, *wlo;
    cudaGetSymbolAddress((void**)&xw1, g_xw1);
    cudaGetSymbolAddress((void**)&h, g_h);
    cudaGetSymbolAddress((void**)&xw2, g_xw2);
    cudaGetSymbolAddress((void**)&ahi, g_Ahi);
    cudaGetSymbolAddress((void**)&alo, g_Alo);
    cudaGetSymbolAddress((void**)&whi, g_Whi);
    cudaGetSymbolAddress((void**)&wlo, g_Wlo);

    const int SMB = SM_ELEMS * 2;
    cudaFuncSetAttribute(gemm_mma, cudaFuncAttributeMaxDynamicSharedMemorySize, SMB);

    // weight conversion (tiny)
    for (int p = 0; p < 4; p++) {
        convW<<<(256 * 256 + 255) / 256, 256>>>(W1[p], whi + WOFF1(p), wlo + WOFF1(p), 256);
        convW<<<(128 * 256 + 255) / 256, 256>>>(W2[p], whi + WOFF2(p), wlo + WOFF2(p), 128);
    }
    convW<<<(128 * 256 + 255) / 256, 256>>>((const float*)d_in[24], whi + WOFFR(0),
                                            wlo + WOFFR(0), 128);
    convW<<<(128 * 256 + 255) / 256, 256>>>((const float*)d_in[26], whi + WOFFR(1),
                                            wlo + WOFFR(1), 128);

    // CSR build
    detect_kernel<<<1, 32>>>(ed[0], ed[1], ed[2], ed[3]);
    zero_counts<<<(4 * NN + 255) / 256, 256>>>();
    build_deg<<<dim3((EE + 255) / 256, 4), 256>>>(ed[0], ed[1], ed[2], ed[3]);
    calc_dinv<<<(4 * NN + 255) / 256, 256>>>();
    scan_p1<<<dim3(NCHUNK, 4), CHUNK>>>();
    scan_p2<<<4, 128>>>();
    scan_p3<<<dim3(NCHUNK, 4), CHUNK>>>();
    build_csr<<<dim3((EE + 255) / 256, 4), 256>>>(ed[0], ed[1], ed[2], ed[3]);

    const int n4 = NN * 256 / 4;
    dim3 cgrid((n4 + 255) / 256);
    dim3 g1(4, (NN + 127) / 128);   // Ntot=256
    dim3 g2(2, (NN + 127) / 128);   // Ntot=128

    for (int p = 0; p < 4; p++) {
        convA<<<cgrid, 256>>>(x[p], ahi, alo, n4);
        gemm_mma<<<g1, 256, SMB>>>(ahi, alo, whi + WOFF1(p), wlo + WOFF1(p), xw1, NN, 256,
                                   nullptr, nullptr, nullptr, 0);
        agg_kernel<256><<<NN, 128>>>(xw1, B1[p], h, p);
        convA<<<cgrid, 256>>>(h, ahi, alo, n4);
        gemm_mma<<<g2, 256, SMB>>>(ahi, alo, whi + WOFF2(p), wlo + WOFF2(p), xw2, NN, 128,
                                   nullptr, nullptr, nullptr, 0);
        agg_kernel<128><<<NN, 128>>>(xw2, B2[p], out + (size_t)(2 + p) * REGSZ, p);
    }
    // comb_l = 0.5*(jl+bl) + x_lnc_jac @ W_res_lnc + b_res_lnc
    convA<<<cgrid, 256>>>(x[0], ahi, alo, n4);
    gemm_mma<<<g2, 256, SMB>>>(ahi, alo, whi + WOFFR(0), wlo + WOFFR(0), out, NN, 128,
                               (const float*)d_in[25], out + (size_t)2 * REGSZ,
                               out + (size_t)4 * REGSZ, 1);
    // comb_p = 0.5*(jp+bp) + x_prot_jac @ W_res_prot + b_res_prot
    convA<<<cgrid, 256>>>(x[1], ahi, alo, n4);
    gemm_mma<<<g2, 256, SMB>>>(ahi, alo, whi + WOFFR(1), wlo + WOFFR(1),
                               out + (size_t)REGSZ, NN, 128, (const float*)d_in[27],
                               out + (size_t)3 * REGSZ, out + (size_t)5 * REGSZ, 1);
}